// round 4
// baseline (speedup 1.0000x reference)
#include <cuda_runtime.h>

#define TT 2048
#define BB 32
#define HH 256
#define G4H 1024
#define GRID_R 128

// ---------------- scratch (static device allocations; no cudaMalloc) ----------------
__device__ float g_xg[(size_t)TT * G4H * BB];   // [t][gate_row][b]  256 MB
__device__ float g_hs0[(size_t)TT * BB * HH];   // layer-0 hidden outputs, 64 MB
__device__ float g_hbuf[2][BB * HH];            // double-buffered h state [buf][b][j]
__device__ unsigned g_ctr[2];                   // per-layer barrier counters
__device__ unsigned g_done[2];                  // per-layer reset handshake
__device__ int g_len[BB];                       // normalized lengths (int32)

// ---------------- lengths normalization: handles int32 OR int64 input buffer ----------
// lengths values are in [1, 2048]. If the buffer is int64 (little-endian), the int32
// word at index 1 is the high word of lengths[0] == 0. If the buffer is int32, word 1
// is lengths[1] >= 1. This reads only 8 bytes for detection (safe for both dtypes).
__global__ void norm_lengths(const int* __restrict__ lenw)
{
    int i = threadIdx.x;            // 0..31
    int is64 = (lenw[1] == 0);
    int v = is64 ? lenw[2 * i] : lenw[i];
    g_len[i] = v;
}

// ---------------- input-projection GEMM: out[t][row][b] = X @ W^T + bias ----------------
// X: [T*B][256] row-major, W: [1024][256], out: [T][1024][32]
__global__ __launch_bounds__(256) void xg_gemm(const float* __restrict__ X,
                                               const float* __restrict__ W,
                                               const float* __restrict__ bias,
                                               float* __restrict__ out)
{
    __shared__ float xs[64][65];
    __shared__ float ws[64][65];
    const int tid = threadIdx.x;
    const int tx = tid & 15;        // tb quad
    const int ty = tid >> 4;        // row quad
    const int tb0 = blockIdx.x * 64;
    const int r0 = blockIdx.y * 64;
    const int lrow = tid >> 4;      // load row 0..15 (x4 passes)
    const int lkq = tid & 15;       // load k-quad

    float acc[4][4];
#pragma unroll
    for (int i = 0; i < 4; i++)
#pragma unroll
        for (int j = 0; j < 4; j++) acc[i][j] = 0.f;

    for (int kt = 0; kt < 256; kt += 64) {
#pragma unroll
        for (int p = 0; p < 4; p++) {
            int row = lrow + p * 16;
            float4 xv = *(const float4*)&X[(size_t)(tb0 + row) * 256 + kt + lkq * 4];
            xs[row][lkq * 4 + 0] = xv.x; xs[row][lkq * 4 + 1] = xv.y;
            xs[row][lkq * 4 + 2] = xv.z; xs[row][lkq * 4 + 3] = xv.w;
            float4 wv = *(const float4*)&W[(size_t)(r0 + row) * 256 + kt + lkq * 4];
            ws[row][lkq * 4 + 0] = wv.x; ws[row][lkq * 4 + 1] = wv.y;
            ws[row][lkq * 4 + 2] = wv.z; ws[row][lkq * 4 + 3] = wv.w;
        }
        __syncthreads();
#pragma unroll 8
        for (int k = 0; k < 64; k++) {
            float xf[4], wf[4];
#pragma unroll
            for (int j = 0; j < 4; j++) xf[j] = xs[tx * 4 + j][k];
#pragma unroll
            for (int i = 0; i < 4; i++) wf[i] = ws[ty * 4 + i][k];
#pragma unroll
            for (int i = 0; i < 4; i++)
#pragma unroll
                for (int j = 0; j < 4; j++) acc[i][j] += wf[i] * xf[j];
        }
        __syncthreads();
    }

    // epilogue: tb group of 4 never crosses a b=32 boundary (tx*4 multiple of 4)
    const int tbb = tb0 + tx * 4;
    const int t = tbb >> 5;
    const int b0 = tbb & 31;
#pragma unroll
    for (int i = 0; i < 4; i++) {
        int row = r0 + ty * 4 + i;
        float bv = bias[row];
        float4 v = make_float4(acc[i][0] + bv, acc[i][1] + bv, acc[i][2] + bv, acc[i][3] + bv);
        *(float4*)&out[(size_t)t * 32768 + row * 32 + b0] = v;
    }
}

// ---------------- persistent recurrent kernel (one layer) ----------------
// Thread (b = tid&31, q = tid>>5): q -> (gate = q>>1, u = q&1); CTA owns units {2*bid, 2*bid+1}.
__global__ __launch_bounds__(256) void lstm_rec(
    const int layer,
    const float* __restrict__ h0,        // [B][H] slice for this layer
    const float* __restrict__ c0,
    const float* __restrict__ Whh,       // [1024][256]
    float* __restrict__ hs_out,          // [T][B][H]
    float* __restrict__ cs_out,          // [T][B][H] or nullptr
    float* __restrict__ hT_out,          // [B][H]
    float* __restrict__ cT_out)
{
    __shared__ float4 w4s[8 * 64];        // 8 gate rows x 256 k (float4)
    __shared__ float4 h4s[32 * 65];       // h staged [b][k4], pitch 65 -> conflict-free
    __shared__ float gsm[8][33];          // gate exchange

    const int tid = threadIdx.x;
    const int b = tid & 31;
    const int q = tid >> 5;
    const int u = q & 1;
    const int j = blockIdx.x * 2 + u;
    const int row = (q >> 1) * 256 + j;   // gate-row in [0,1024)

    // load this CTA's 8 W_hh rows into smem (once)
    {
        const float4* W4 = (const float4*)Whh;
#pragma unroll
        for (int p = 0; p < 2; p++) {
            int i = tid + p * 256;        // 0..511
            int qq = i >> 6, k4 = i & 63;
            int rr = (qq >> 1) * 256 + blockIdx.x * 2 + (qq & 1);
            w4s[i] = W4[(size_t)rr * 64 + k4];
        }
    }

    // state owners: tid < 64 -> (u = tid>>5, b)
    float c_reg = 0.f, h_reg = 0.f;
    int len_b = 0;
    if (tid < 64) {
        h_reg = h0[b * 256 + j];
        c_reg = c0[b * 256 + j];
        len_b = g_len[b];
        __stcg(&g_hbuf[0][b * 256 + j], h_reg);   // L2-coherent write
    }
    __threadfence();
    __syncthreads();
    if (tid == 0) atomicAdd(&g_ctr[layer], 1);

    unsigned target = GRID_R;
    volatile unsigned* ctr = (volatile unsigned*)&g_ctr[layer];

    for (int t = 0; t < TT; t++) {
        // prefetch xg (independent of barrier) to hide DRAM latency behind sync
        float xgv = __ldg(&g_xg[(size_t)t * 32768 + row * 32 + b]);

        if (tid == 0) {
            while (*ctr < target) { }
            __threadfence();
        }
        __syncthreads();
        target += GRID_R;

        // stage full h into smem (L2-coherent loads; cross-SM producer)
        {
            const float4* hb = (const float4*)g_hbuf[t & 1];
#pragma unroll
            for (int p = 0; p < 8; p++) {
                int i = tid + p * 256;    // 0..2047
                h4s[(i >> 6) * 65 + (i & 63)] = __ldcg(&hb[i]);
            }
        }
        __syncthreads();

        // dot: gates[row][b] = xg + sum_k h[b][k]*Whh[row][k]
        float acc = 0.f;
        {
            const float4* hr = &h4s[b * 65];
            const float4* wr = &w4s[q * 64];
#pragma unroll 16
            for (int k4 = 0; k4 < 64; k4++) {
                float4 hv = hr[k4];
                float4 wv = wr[k4];
                acc += hv.x * wv.x;
                acc += hv.y * wv.y;
                acc += hv.z * wv.z;
                acc += hv.w * wv.w;
            }
        }
        acc += xgv;
        gsm[q][b] = acc;
        __syncthreads();

        if (tid < 64) {
            float gi = gsm[0 + u][b];
            float gf = gsm[2 + u][b];
            float gg = gsm[4 + u][b];
            float go = gsm[6 + u][b];
            float i_ = 1.f / (1.f + __expf(-gi));
            float f_ = 1.f / (1.f + __expf(-gf));
            float g_ = tanhf(gg);
            float o_ = 1.f / (1.f + __expf(-go));
            float cn = f_ * c_reg + i_ * g_;
            float hn = o_ * tanhf(cn);
            if (t < len_b) { c_reg = cn; h_reg = hn; }
            int oidx = t * 8192 + b * 256 + j;
            hs_out[oidx] = h_reg;
            if (cs_out) cs_out[oidx] = c_reg;
            __stcg(&g_hbuf[(t + 1) & 1][b * 256 + j], h_reg);  // L2-coherent write
            __threadfence();
        }
        __syncthreads();
        if (tid == 0) atomicAdd(&g_ctr[layer], 1);
    }

    if (tid < 64) {
        hT_out[b * 256 + j] = h_reg;
        cT_out[b * 256 + j] = c_reg;
    }

    // reset handshake so graph replays start from a clean counter
    __syncthreads();
    if (tid == 0) {
        unsigned d = atomicAdd(&g_done[layer], 1);
        if (d == GRID_R - 1) {
            g_ctr[layer] = 0;
            __threadfence();
            g_done[layer] = 0;
        }
    }
}

// ---------------- launch ----------------
extern "C" void kernel_launch(void* const* d_in, const int* in_sizes, int n_in,
                              void* d_out, int out_size)
{
    const float* x        = (const float*)d_in[0];
    const int*   lenw     = (const int*)d_in[1];   // int32 words; dtype detected on device
    const float* h0       = (const float*)d_in[2];
    const float* c0       = (const float*)d_in[3];
    const float* Wih0     = (const float*)d_in[4];
    const float* Whh0     = (const float*)d_in[5];
    const float* b0v      = (const float*)d_in[6];
    const float* Wih1     = (const float*)d_in[7];
    const float* Whh1     = (const float*)d_in[8];
    const float* b1v      = (const float*)d_in[9];
    float* out = (float*)d_out;

    float* xg_p = nullptr;
    float* hs0_p = nullptr;
    cudaGetSymbolAddress((void**)&xg_p, g_xg);
    cudaGetSymbolAddress((void**)&hs0_p, g_hs0);

    const size_t SEQ = (size_t)TT * BB * HH;   // 16,777,216
    float* hs_final = out;                     // [T][B][H]
    float* cs_final = out + SEQ;               // [T][B][H]
    float* hT = out + 2 * SEQ;                 // [2][B][H]
    float* cT = out + 2 * SEQ + 2 * BB * HH;   // [2][B][H]

    dim3 ggrid(1024, 16);

    norm_lengths<<<1, 32>>>(lenw);

    // layer 0
    xg_gemm<<<ggrid, 256>>>(x, Wih0, b0v, xg_p);
    lstm_rec<<<GRID_R, 256>>>(0, h0, c0, Whh0,
                              hs0_p, nullptr, hT, cT);
    // layer 1 (input = layer-0 hidden states)
    xg_gemm<<<ggrid, 256>>>(hs0_p, Wih1, b1v, xg_p);
    lstm_rec<<<GRID_R, 256>>>(1, h0 + BB * HH, c0 + BB * HH, Whh1,
                              hs_final, cs_final, hT + BB * HH, cT + BB * HH);
}